// round 4
// baseline (speedup 1.0000x reference)
#include <cuda_runtime.h>
#include <cstdint>

// Problem constants (fixed shapes for this problem)
#define DIMV   96
#define PVOX   (96*96*96)          // 884736 spatial positions
#define CCH    32
#define NB     2
#define NPERB  30000
#define NVTOT  60000
#define VPB    16                  // vertices per block group (= warps per block)
#define NGROUPS (NVTOT/VPB)        // 3750
#define ITOT   864                 // C*27
#define I4TOT  216
#define I4PAD  224                 // padded so 224 % 16 warps == 14 per warp
#define FSTRIDE 896                // padded feats row (divisible by 4 -> 16B aligned)

#define WQ_FLOATS  (I4PAD*32*4)    // 28672 floats (114688 B)
#define FS_FLOATS  (VPB*FSTRIDE)   // 14336 floats (57344 B)
#define PART_FLOATS (16*VPB*32)    // 8192 floats (32768 B)
#define SMEM_FLOATS (WQ_FLOATS+FS_FLOATS+PART_FLOATS)
#define SMEM_BYTES  (SMEM_FLOATS*4)  // 204800 B

// Scratch: transposed voxel features (B, H, W, D, C) - channels contiguous
__device__ float g_vt[(size_t)NB * PVOX * CCH];

// Packed fp32x2 FMA (Blackwell): d = a*b + c on two fp32 lanes in one instr
static __device__ __forceinline__ unsigned long long ffma2(
    unsigned long long a, unsigned long long b, unsigned long long c) {
    unsigned long long d;
    asm("fma.rn.f32x2 %0, %1, %2, %3;" : "=l"(d) : "l"(a), "l"(b), "l"(c));
    return d;
}
static __device__ __forceinline__ void unpack2(unsigned long long v, float& x, float& y) {
    asm("mov.b64 {%0, %1}, %2;" : "=f"(x), "=f"(y) : "l"(v));
}

// ---------------------------------------------------------------------------
// Kernel 1: transpose (B,C,P) -> (B,P,C), tiled 32x32 through smem
// ---------------------------------------------------------------------------
__global__ void __launch_bounds__(256) transpose_kernel(
    const float* __restrict__ in, float* __restrict__ vt) {
    __shared__ float tile[32][33];
    int pt = blockIdx.x;              // 0..PVOX/32-1
    int b  = blockIdx.y;              // 0..NB-1
    int p0 = pt * 32;
    int tx = threadIdx.x, ty = threadIdx.y;  // (32, 8)

    const float* ib = in + (size_t)b * CCH * PVOX;
#pragma unroll
    for (int cc = ty; cc < 32; cc += 8)
        tile[cc][tx] = ib[(size_t)cc * PVOX + p0 + tx];
    __syncthreads();
    float* ob = vt + ((size_t)b * PVOX + p0) * CCH;
#pragma unroll
    for (int pp = ty; pp < 32; pp += 8)
        ob[(size_t)pp * CCH + tx] = tile[tx][pp];
}

// ---------------------------------------------------------------------------
// Kernel 2: persistent fused sample + conv.
//  Block = 512 threads = 16 warps; each group = 16 vertices.
//  Phase 1: warp-per-vertex separable trilinear over a clamped 4x4x4 window,
//           lane = input channel; feats -> smem [v][FSTRIDE], i = c*27+k.
//  Phase 2: lane = output channel; warp w handles i4 in [w*14, w*14+14) for
//           ALL 16 vertices (W smem reads amortized 16x); packed f32x2 FMA.
//  Phase 3: cross-warp reduction of 16 partials + bias, coalesced store.
// ---------------------------------------------------------------------------
__global__ void __launch_bounds__(512, 1) fused_kernel(
    const float* __restrict__ vt,
    const float* __restrict__ verts,
    const float* __restrict__ Wg,      // (32,32,1,27) -> o*864 + c*27 + k
    const float* __restrict__ bias,
    float* __restrict__ out) {
    extern __shared__ float sm[];
    float* Wq   = sm;                       // [I4PAD][32][4]
    float* fs   = sm + WQ_FLOATS;           // [VPB][FSTRIDE]
    float* part = sm + WQ_FLOATS + FS_FLOATS; // [16 warps][VPB][32]

    const int tid  = threadIdx.x;
    const int warp = tid >> 5;
    const int lane = tid & 31;

    // ---- one-time per block: stage W into smem (vector layout), zero pads --
    for (int g = tid; g < 32 * I4PAD; g += 512) {
        int o  = g / I4PAD;
        int i4 = g - o * I4PAD;
        float4 w = make_float4(0.f, 0.f, 0.f, 0.f);
        if (i4 < I4TOT) w = *reinterpret_cast<const float4*>(Wg + (size_t)o * ITOT + i4 * 4);
        *reinterpret_cast<float4*>(Wq + ((size_t)i4 * 32 + o) * 4) = w;
    }
    // zero feats tail [864, 896) for every vertex slot (never rewritten)
    {
        int v = tid >> 5;           // 0..15
        fs[v * FSTRIDE + ITOT + lane] = 0.f;
    }
    __syncthreads();

    for (int grp = blockIdx.x; grp < NGROUPS; grp += gridDim.x) {
        const int vglob = grp * VPB + warp;
        const int b = vglob / NPERB;
        const int n = vglob - b * NPERB;

        // ================= Phase 1: separable trilinear, lane = channel =====
        const float vx = verts[(size_t)vglob * 3 + 0];  // -> D axis
        const float vy = verts[(size_t)vglob * 3 + 1];  // -> W axis
        const float vz = verts[(size_t)vglob * 3 + 2];  // -> H axis

        float fx, fy, fz;
        int xo[4], yo[4], zo[4];
        {
            float f = fminf(fmaxf((vx + 1.f) * (0.5f * 95.f), 0.f), 95.f);
            int i0 = (int)f; fx = f - (float)i0;
#pragma unroll
            for (int j = 0; j < 4; j++) xo[j] = min(max(i0 - 1 + j, 0), 95) * CCH;
        }
        {
            float f = fminf(fmaxf((vy + 1.f) * (0.5f * 95.f), 0.f), 95.f);
            int i0 = (int)f; fy = f - (float)i0;
#pragma unroll
            for (int j = 0; j < 4; j++) yo[j] = min(max(i0 - 1 + j, 0), 95) * (DIMV * CCH);
        }
        {
            float f = fminf(fmaxf((vz + 1.f) * (0.5f * 95.f), 0.f), 95.f);
            int i0 = (int)f; fz = f - (float)i0;
#pragma unroll
            for (int j = 0; j < 4; j++) zo[j] = min(max(i0 - 1 + j, 0), 95) * (DIMV * DIMV * CCH);
        }
        const float omfz = 1.f - fz;
        const float* bp = vt + (size_t)b * ((size_t)PVOX * CCH) + lane;

        float acc[27];
#pragma unroll
        for (int kk = 0; kk < 27; kk++) acc[kk] = 0.f;

#pragma unroll
        for (int jz = 0; jz < 4; jz++) {
            float t4[12];
#pragma unroll
            for (int jy = 0; jy < 4; jy++) {
                const float* r = bp + zo[jz] + yo[jy];
                float a0 = __ldg(r + xo[0]);
                float a1 = __ldg(r + xo[1]);
                float a2 = __ldg(r + xo[2]);
                float a3 = __ldg(r + xo[3]);
                t4[jy * 3 + 0] = a0 + fx * (a1 - a0);
                t4[jy * 3 + 1] = a1 + fx * (a2 - a1);
                t4[jy * 3 + 2] = a2 + fx * (a3 - a2);
            }
#pragma unroll
            for (int dy = 0; dy < 3; dy++) {
#pragma unroll
                for (int dxx = 0; dxx < 3; dxx++) {
                    float a  = t4[dy * 3 + dxx];
                    float bq = t4[(dy + 1) * 3 + dxx];
                    float ly = a + fy * (bq - a);
                    // plane jz feeds feats[dz=jz] with (1-fz), feats[dz=jz-1] with fz
                    if (jz < 3) acc[dxx * 9 + dy * 3 + jz]     += omfz * ly;
                    if (jz > 0) acc[dxx * 9 + dy * 3 + (jz-1)] += fz   * ly;
                }
            }
        }
        // write feats: i = c*27 + k, k = dxi*9 + dyi*3 + dzi (matches W layout)
        {
            float* fr = fs + warp * FSTRIDE + lane * 27;
#pragma unroll
            for (int kk = 0; kk < 27; kk++) fr[kk] = acc[kk];
        }
        __syncthreads();

        // ================= Phase 2: conv, lane = output channel =============
        {
            unsigned long long acc2[VPB];
#pragma unroll
            for (int v = 0; v < VPB; v++) acc2[v] = 0ull;

            const int i4base = warp * (I4PAD / 16);   // 14 groups per warp
            for (int t = 0; t < I4PAD / 16; t++) {
                const int i4 = i4base + t;
                ulonglong2 w2 = *reinterpret_cast<const ulonglong2*>(
                    Wq + ((size_t)i4 * 32 + lane) * 4);
#pragma unroll
                for (int v = 0; v < VPB; v++) {
                    ulonglong2 f2v = *reinterpret_cast<const ulonglong2*>(
                        fs + (size_t)v * FSTRIDE + i4 * 4);
                    acc2[v] = ffma2(w2.x, f2v.x, acc2[v]);
                    acc2[v] = ffma2(w2.y, f2v.y, acc2[v]);
                }
            }
#pragma unroll
            for (int v = 0; v < VPB; v++) {
                float x, y; unpack2(acc2[v], x, y);
                part[((size_t)warp * VPB + v) * 32 + lane] = x + y;
            }
        }
        __syncthreads();

        // ================= Phase 3: reduce partials + bias, store ===========
        {
            float s = __ldg(bias + lane);
#pragma unroll
            for (int w2 = 0; w2 < 16; w2++)
                s += part[((size_t)w2 * VPB + warp) * 32 + lane];
            out[((size_t)b * NPERB + n) * 32 + lane] = s;
        }
        __syncthreads();  // protect `part` before next iteration's conv
    }
}

// ---------------------------------------------------------------------------
extern "C" void kernel_launch(void* const* d_in, const int* in_sizes, int n_in,
                              void* d_out, int out_size) {
    const float* vox   = (const float*)d_in[0];   // (2,32,96,96,96)
    const float* verts = (const float*)d_in[1];   // (2,30000,3)
    const float* Wg    = (const float*)d_in[2];   // (32,32,1,27)
    const float* bias  = (const float*)d_in[3];   // (32,)
    float* out = (float*)d_out;

    float* vt = nullptr;
    cudaGetSymbolAddress((void**)&vt, g_vt);

    cudaFuncSetAttribute(fused_kernel,
                         cudaFuncAttributeMaxDynamicSharedMemorySize, SMEM_BYTES);

    transpose_kernel<<<dim3(PVOX / 32, NB), dim3(32, 8)>>>(vox, vt);
    fused_kernel<<<152, 512, SMEM_BYTES>>>(vt, verts, Wg, bias, out);
}